// round 6
// baseline (speedup 1.0000x reference)
#include <cuda_runtime.h>
#include <cuda_fp16.h>
#include <cstdint>

#define BB 24
#define DM 128
#define HH 8
#define DK 16
#define LL 512
#define HB (HH*BB)   // 192

__device__ float g_Q[HB*DK*LL];       // [hb][k][l]
__device__ float g_K[HB*DK*LL];
__device__ float g_V[HB*DK*LL];
__device__ float g_head[BB*DM*LL];    // [b][h*16+v][l]

// ---- mma/ldmatrix helpers ----
__device__ __forceinline__ uint32_t smem_u32(const void* p) {
    uint32_t a;
    asm("{ .reg .u64 t; cvta.to.shared.u64 t, %1; cvt.u32.u64 %0, t; }" : "=r"(a) : "l"(p));
    return a;
}
__device__ __forceinline__ void ldsm4(uint32_t* r, uint32_t a) {
    asm volatile("ldmatrix.sync.aligned.m8n8.x4.shared.b16 {%0,%1,%2,%3}, [%4];"
        : "=r"(r[0]), "=r"(r[1]), "=r"(r[2]), "=r"(r[3]) : "r"(a));
}
__device__ __forceinline__ void mma_f16(float* d, const uint32_t* a, const uint32_t* b) {
    asm volatile("mma.sync.aligned.m16n8k16.row.col.f32.f16.f16.f32 "
        "{%0,%1,%2,%3}, {%4,%5,%6,%7}, {%8,%9}, {%0,%1,%2,%3};"
        : "+f"(d[0]), "+f"(d[1]), "+f"(d[2]), "+f"(d[3])
        : "r"(a[0]), "r"(a[1]), "r"(a[2]), "r"(a[3]), "r"(b[0]), "r"(b[1]));
}
__device__ __forceinline__ float ex2f(float x) {
    float r; asm("ex2.approx.f32 %0, %1;" : "=f"(r) : "f"(x)); return r;
}
__device__ __forceinline__ void packhl(float p0, float p1, uint32_t& h, uint32_t& l) {
    __half2 hh = __floats2half2_rn(p0, p1);
    float2 f = __half22float2(hh);
    __half2 ll = __floats2half2_rn(p0 - f.x, p1 - f.y);
    h = *(uint32_t*)&hh; l = *(uint32_t*)&ll;
}
__device__ __forceinline__ void split1(float v, __half& h, __half& l) {
    h = __float2half_rn(v);
    l = __float2half_rn(v - __half2float(h));
}

// =====================================================================
// Kernel 1: QKV projection via mma.sync fp16 hi/lo (3-term).
// Grid 192 (hb), 256 threads = 8 warps x 16 l-cols.
// A = [Wq;Wk;Wv] 48x128 (3 m16 tiles -> Q,K,V). B = x chunk [l][d] transposed.
// =====================================================================
#define QW_H 0          // 48*136*2  = 13056
#define QW_L 13056
#define QX_H 26112      // 128*136*2 = 34816
#define QX_L 60928
#define Q_SMEM 95744

__global__ __launch_bounds__(256) void k_qkv(const float* __restrict__ x,
                                             const float* __restrict__ Wq,
                                             const float* __restrict__ Wk,
                                             const float* __restrict__ Wv)
{
    extern __shared__ char smc[];
    const uint32_t su = smem_u32(smc);
    __half* sWh = (__half*)(smc + QW_H);
    __half* sWl = (__half*)(smc + QW_L);
    __half* sXh = (__half*)(smc + QX_H);
    __half* sXl = (__half*)(smc + QX_L);
    const int t = threadIdx.x, w = t >> 5, ln = t & 31;
    const int hb = blockIdx.x, b = hb % BB;
    const int rsel = ln & 15;
    const uint32_t csel = (uint32_t)(ln >> 4) * 16;

    // stage W (48 rows x 128), hi/lo, pitch 136 halves
    for (int i = t; i < 6144; i += 256) {
        int r = i >> 7, c = i & 127;
        const float* src = (r < 16) ? (Wq + (size_t)hb*2048 + r*128)
                         : (r < 32) ? (Wk + (size_t)hb*2048 + (r-16)*128)
                                    : (Wv + (size_t)hb*2048 + (r-32)*128);
        __half hi, lo; split1(src[c], hi, lo);
        sWh[r*136 + c] = hi; sWl[r*136 + c] = lo;
    }

    for (int lt = 0; lt < 4; ++lt) {
        __syncthreads();
        // stage x chunk transposed: sX[l][d], l in [0,128)
        for (int i = t; i < 4096; i += 256) {
            int d = i >> 5, l4 = i & 31;
            float4 xv = *(const float4*)(x + (size_t)b*DM*LL + (size_t)d*LL + lt*128 + l4*4);
            __half h0,l0,h1,l1,h2,l2,h3,l3;
            split1(xv.x,h0,l0); split1(xv.y,h1,l1); split1(xv.z,h2,l2); split1(xv.w,h3,l3);
            int lr = l4*4;
            sXh[(lr  )*136 + d] = h0; sXl[(lr  )*136 + d] = l0;
            sXh[(lr+1)*136 + d] = h1; sXl[(lr+1)*136 + d] = l1;
            sXh[(lr+2)*136 + d] = h2; sXl[(lr+2)*136 + d] = l2;
            sXh[(lr+3)*136 + d] = h3; sXl[(lr+3)*136 + d] = l3;
        }
        __syncthreads();

        float acc[3][2][4];
        #pragma unroll
        for (int mt = 0; mt < 3; ++mt)
            #pragma unroll
            for (int nt = 0; nt < 2; ++nt)
                #pragma unroll
                for (int r = 0; r < 4; ++r) acc[mt][nt][r] = 0.f;

        #pragma unroll
        for (int kt = 0; kt < 8; ++kt) {
            uint32_t bh[2][2], bl[2][2], r4[4];
            uint32_t ad = su + QX_H + (uint32_t)((w*16 + rsel)*272) + csel + kt*32;
            ldsm4(r4, ad);
            bh[0][0]=r4[0]; bh[0][1]=r4[2]; bh[1][0]=r4[1]; bh[1][1]=r4[3];
            ldsm4(r4, ad + (QX_L - QX_H));
            bl[0][0]=r4[0]; bl[0][1]=r4[2]; bl[1][0]=r4[1]; bl[1][1]=r4[3];
            #pragma unroll
            for (int mt = 0; mt < 3; ++mt) {
                uint32_t ah[4], al[4];
                uint32_t aad = su + QW_H + (uint32_t)((mt*16 + rsel)*272) + csel + kt*32;
                ldsm4(ah, aad);
                ldsm4(al, aad + (QW_L - QW_H));
                #pragma unroll
                for (int nt = 0; nt < 2; ++nt) {
                    mma_f16(acc[mt][nt], ah, bh[nt]);
                    mma_f16(acc[mt][nt], ah, bl[nt]);
                    mma_f16(acc[mt][nt], al, bh[nt]);
                }
            }
        }

        // epilogue: mt 0/1/2 -> Q/K/V rows
        #pragma unroll
        for (int mt = 0; mt < 3; ++mt) {
            float* dst = (mt == 0) ? g_Q : (mt == 1) ? g_K : g_V;
            dst += (size_t)hb * 8192;
            #pragma unroll
            for (int nt = 0; nt < 2; ++nt) {
                int rr = ln >> 2;
                int cc = lt*128 + w*16 + nt*8 + (ln & 3)*2;
                float2 v0; v0.x = acc[mt][nt][0]; v0.y = acc[mt][nt][1];
                float2 v1; v1.x = acc[mt][nt][2]; v1.y = acc[mt][nt][3];
                *(float2*)&dst[(size_t)rr*512 + cc]     = v0;
                *(float2*)&dst[(size_t)(rr+8)*512 + cc] = v1;
            }
        }
    }
}

// =====================================================================
// Kernel 2: attention via mma.sync fp16 hi/lo split, flash-style.
// (unchanged from R5 pass)
// =====================================================================
#define AT_QH 0
#define AT_QL 24576
#define AT_KH 49152
#define AT_KL 73728
#define AT_VH 98304
#define AT_VL 114944
#define AT_SMEM 131584

__global__ __launch_bounds__(512) void k_attn()
{
    extern __shared__ char smc[];
    const uint32_t su = smem_u32(smc);
    const int t = threadIdx.x, w = t >> 5, ln = t & 31;
    const int hb = blockIdx.x, b = hb % BB, h = hb / BB;

    __half* sQh = (__half*)(smc + AT_QH);
    __half* sQl = (__half*)(smc + AT_QL);
    __half* sKh = (__half*)(smc + AT_KH);
    __half* sKl = (__half*)(smc + AT_KL);
    __half* sVh = (__half*)(smc + AT_VH);
    __half* sVl = (__half*)(smc + AT_VL);

    const float* gq = g_Q + (size_t)hb * 8192;
    const float* gk = g_K + (size_t)hb * 8192;
    const float* gv = g_V + (size_t)hb * 8192;

    for (int i = t; i < 8192; i += 512) {
        int k = i >> 9, l = i & 511;
        float q = gq[i];
        __half qh = __float2half_rn(q);
        sQh[l*24 + k] = qh; sQl[l*24 + k] = __float2half_rn(q - __half2float(qh));
        float kk = gk[i];
        __half khh = __float2half_rn(kk);
        sKh[l*24 + k] = khh; sKl[l*24 + k] = __float2half_rn(kk - __half2float(khh));
        float v = gv[i];
        __half vh = __float2half_rn(v);
        sVh[k*520 + l] = vh; sVl[k*520 + l] = __float2half_rn(v - __half2float(vh));
    }
    __syncthreads();

    const int rsel = ln & 15;
    const uint32_t csel = (uint32_t)(ln >> 4) * 16;

    uint32_t kh[2][4], kl[2][4];
    #pragma unroll
    for (int mt = 0; mt < 2; ++mt) {
        uint32_t ad = su + AT_KH + (uint32_t)((w*32 + mt*16 + rsel) * 48) + csel;
        ldsm4(kh[mt], ad);
        ldsm4(kl[mt], ad + (AT_KL - AT_KH));
    }

    float mx[2][2], dn[2][2], O[2][2][4];
    #pragma unroll
    for (int mt = 0; mt < 2; ++mt)
        #pragma unroll
        for (int j = 0; j < 2; ++j) {
            mx[mt][j] = -1e30f; dn[mt][j] = 0.f;
            #pragma unroll
            for (int r = 0; r < 4; ++r) O[mt][j][r] = 0.f;
        }

    const float C = 0.36067376022224085f;   // 0.25 * log2(e)

    for (int c = 0; c < 16; ++c) {
        uint32_t qbh[4][2], qbl[4][2];
        #pragma unroll
        for (int q = 0; q < 2; ++q) {
            uint32_t r4[4];
            uint32_t ad = su + AT_QH + (uint32_t)((c*32 + q*16 + rsel) * 48) + csel;
            ldsm4(r4, ad);
            qbh[2*q][0]=r4[0]; qbh[2*q][1]=r4[2]; qbh[2*q+1][0]=r4[1]; qbh[2*q+1][1]=r4[3];
            ldsm4(r4, ad + (AT_QL - AT_QH));
            qbl[2*q][0]=r4[0]; qbl[2*q][1]=r4[2]; qbl[2*q+1][0]=r4[1]; qbl[2*q+1][1]=r4[3];
        }

        float s[2][4][4];
        #pragma unroll
        for (int mt = 0; mt < 2; ++mt)
            #pragma unroll
            for (int nt = 0; nt < 4; ++nt) {
                #pragma unroll
                for (int r = 0; r < 4; ++r) s[mt][nt][r] = 0.f;
                mma_f16(s[mt][nt], kh[mt], qbh[nt]);
                mma_f16(s[mt][nt], kh[mt], qbl[nt]);
                mma_f16(s[mt][nt], kl[mt], qbh[nt]);
            }

        #pragma unroll
        for (int mt = 0; mt < 2; ++mt) {
            float cA = -1e30f, cB = -1e30f;
            #pragma unroll
            for (int nt = 0; nt < 4; ++nt) {
                cA = fmaxf(cA, fmaxf(s[mt][nt][0], s[mt][nt][1]));
                cB = fmaxf(cB, fmaxf(s[mt][nt][2], s[mt][nt][3]));
            }
            cA = fmaxf(cA, __shfl_xor_sync(0xffffffffu, cA, 1));
            cA = fmaxf(cA, __shfl_xor_sync(0xffffffffu, cA, 2));
            cB = fmaxf(cB, __shfl_xor_sync(0xffffffffu, cB, 1));
            cB = fmaxf(cB, __shfl_xor_sync(0xffffffffu, cB, 2));
            float mA = fmaxf(mx[mt][0], cA), mB = fmaxf(mx[mt][1], cB);
            float sA = ex2f((mx[mt][0] - mA) * C), sB = ex2f((mx[mt][1] - mB) * C);
            mx[mt][0] = mA; mx[mt][1] = mB;
            dn[mt][0] *= sA; dn[mt][1] *= sB;
            #pragma unroll
            for (int vt = 0; vt < 2; ++vt) {
                O[mt][vt][0] *= sA; O[mt][vt][1] *= sA;
                O[mt][vt][2] *= sB; O[mt][vt][3] *= sB;
            }
            #pragma unroll
            for (int nt = 0; nt < 4; ++nt) {
                float p0 = ex2f((s[mt][nt][0] - mA) * C);
                float p1 = ex2f((s[mt][nt][1] - mA) * C);
                float p2 = ex2f((s[mt][nt][2] - mB) * C);
                float p3 = ex2f((s[mt][nt][3] - mB) * C);
                dn[mt][0] += p0 + p1; dn[mt][1] += p2 + p3;
                s[mt][nt][0] = p0; s[mt][nt][1] = p1;
                s[mt][nt][2] = p2; s[mt][nt][3] = p3;
            }
        }

        #pragma unroll
        for (int st = 0; st < 2; ++st) {
            uint32_t vbh[2][2], vbl[2][2], r4[4];
            uint32_t ad = su + AT_VH + (uint32_t)(rsel * 1040 + (c*32 + st*16) * 2) + csel;
            ldsm4(r4, ad);
            vbh[0][0]=r4[0]; vbh[0][1]=r4[2]; vbh[1][0]=r4[1]; vbh[1][1]=r4[3];
            ldsm4(r4, ad + (AT_VL - AT_VH));
            vbl[0][0]=r4[0]; vbl[0][1]=r4[2]; vbl[1][0]=r4[1]; vbl[1][1]=r4[3];

            #pragma unroll
            for (int mt = 0; mt < 2; ++mt) {
                uint32_t ah[4], al[4];
                packhl(s[mt][2*st][0],   s[mt][2*st][1],   ah[0], al[0]);
                packhl(s[mt][2*st][2],   s[mt][2*st][3],   ah[1], al[1]);
                packhl(s[mt][2*st+1][0], s[mt][2*st+1][1], ah[2], al[2]);
                packhl(s[mt][2*st+1][2], s[mt][2*st+1][3], ah[3], al[3]);
                #pragma unroll
                for (int vt = 0; vt < 2; ++vt) {
                    mma_f16(O[mt][vt], ah, vbh[vt]);
                    mma_f16(O[mt][vt], ah, vbl[vt]);
                    mma_f16(O[mt][vt], al, vbh[vt]);
                }
            }
        }
    }

    #pragma unroll
    for (int mt = 0; mt < 2; ++mt)
        #pragma unroll
        for (int j = 0; j < 2; ++j) {
            dn[mt][j] += __shfl_xor_sync(0xffffffffu, dn[mt][j], 1);
            dn[mt][j] += __shfl_xor_sync(0xffffffffu, dn[mt][j], 2);
        }

    float* dst = g_head + ((size_t)b * DM + h * DK) * LL;
    #pragma unroll
    for (int mt = 0; mt < 2; ++mt)
        #pragma unroll
        for (int vt = 0; vt < 2; ++vt)
            #pragma unroll
            for (int r = 0; r < 4; ++r) {
                int m = w*32 + mt*16 + (ln >> 2) + ((r >> 1) & 1) * 8;
                int v = vt*8 + (ln & 3)*2 + (r & 1);
                dst[(size_t)v * LL + m] = O[mt][vt][r] / dn[mt][(r >> 1) & 1];
            }
}

// =====================================================================
// Kernel 3: out[b] = Wo[b] @ head[b] via mma.sync fp16 hi/lo (3-term).
// Grid (4 lt, 24 b), 256 threads = 8 warps x 16 l-cols. 8 m16 tiles.
// =====================================================================
#define OW_H 0          // 128*136*2 = 34816
#define OW_L 34816
#define OX_H 69632
#define OX_L 104448
#define O_SMEM 139264

__global__ __launch_bounds__(256) void k_out(const float* __restrict__ Wo,
                                             float* __restrict__ out)
{
    extern __shared__ char smc[];
    const uint32_t su = smem_u32(smc);
    __half* sWh = (__half*)(smc + OW_H);
    __half* sWl = (__half*)(smc + OW_L);
    __half* sXh = (__half*)(smc + OX_H);
    __half* sXl = (__half*)(smc + OX_L);
    const int t = threadIdx.x, w = t >> 5, ln = t & 31;
    const int lt = blockIdx.x, b = blockIdx.y;
    const int rsel = ln & 15;
    const uint32_t csel = (uint32_t)(ln >> 4) * 16;

    for (int i = t; i < 16384; i += 256) {
        int r = i >> 7, c = i & 127;
        __half hi, lo; split1(Wo[(size_t)b*16384 + i], hi, lo);
        sWh[r*136 + c] = hi; sWl[r*136 + c] = lo;
    }
    for (int i = t; i < 4096; i += 256) {
        int d = i >> 5, l4 = i & 31;
        float4 xv = *(const float4*)(g_head + (size_t)b*DM*LL + (size_t)d*LL + lt*128 + l4*4);
        __half h0,l0,h1,l1,h2,l2,h3,l3;
        split1(xv.x,h0,l0); split1(xv.y,h1,l1); split1(xv.z,h2,l2); split1(xv.w,h3,l3);
        int lr = l4*4;
        sXh[(lr  )*136 + d] = h0; sXl[(lr  )*136 + d] = l0;
        sXh[(lr+1)*136 + d] = h1; sXl[(lr+1)*136 + d] = l1;
        sXh[(lr+2)*136 + d] = h2; sXl[(lr+2)*136 + d] = l2;
        sXh[(lr+3)*136 + d] = h3; sXl[(lr+3)*136 + d] = l3;
    }
    __syncthreads();

    float acc[8][2][4];
    #pragma unroll
    for (int mt = 0; mt < 8; ++mt)
        #pragma unroll
        for (int nt = 0; nt < 2; ++nt)
            #pragma unroll
            for (int r = 0; r < 4; ++r) acc[mt][nt][r] = 0.f;

    #pragma unroll
    for (int kt = 0; kt < 8; ++kt) {
        uint32_t bh[2][2], bl[2][2], r4[4];
        uint32_t ad = su + OX_H + (uint32_t)((w*16 + rsel)*272) + csel + kt*32;
        ldsm4(r4, ad);
        bh[0][0]=r4[0]; bh[0][1]=r4[2]; bh[1][0]=r4[1]; bh[1][1]=r4[3];
        ldsm4(r4, ad + (OX_L - OX_H));
        bl[0][0]=r4[0]; bl[0][1]=r4[2]; bl[1][0]=r4[1]; bl[1][1]=r4[3];
        #pragma unroll
        for (int mt = 0; mt < 8; ++mt) {
            uint32_t ah[4], al[4];
            uint32_t aad = su + OW_H + (uint32_t)((mt*16 + rsel)*272) + csel + kt*32;
            ldsm4(ah, aad);
            ldsm4(al, aad + (OW_L - OW_H));
            #pragma unroll
            for (int nt = 0; nt < 2; ++nt) {
                mma_f16(acc[mt][nt], ah, bh[nt]);
                mma_f16(acc[mt][nt], ah, bl[nt]);
                mma_f16(acc[mt][nt], al, bh[nt]);
            }
        }
    }

    #pragma unroll
    for (int mt = 0; mt < 8; ++mt)
        #pragma unroll
        for (int nt = 0; nt < 2; ++nt) {
            int rr = mt*16 + (ln >> 2);
            int cc = lt*128 + w*16 + nt*8 + (ln & 3)*2;
            float2 v0; v0.x = acc[mt][nt][0]; v0.y = acc[mt][nt][1];
            float2 v1; v1.x = acc[mt][nt][2]; v1.y = acc[mt][nt][3];
            *(float2*)&out[(size_t)b*DM*LL + (size_t)rr*512 + cc]     = v0;
            *(float2*)&out[(size_t)b*DM*LL + (size_t)(rr+8)*512 + cc] = v1;
        }
}

// =====================================================================
extern "C" void kernel_launch(void* const* d_in, const int* in_sizes, int n_in,
                              void* d_out, int out_size)
{
    const float* x  = (const float*)d_in[0];
    const float* Wq = (const float*)d_in[1];
    const float* Wk = (const float*)d_in[2];
    const float* Wv = (const float*)d_in[3];
    const float* Wo = (const float*)d_in[4];
    float* out = (float*)d_out;

    cudaFuncSetAttribute(k_qkv,  cudaFuncAttributeMaxDynamicSharedMemorySize, Q_SMEM);
    cudaFuncSetAttribute(k_attn, cudaFuncAttributeMaxDynamicSharedMemorySize, AT_SMEM);
    cudaFuncSetAttribute(k_out,  cudaFuncAttributeMaxDynamicSharedMemorySize, O_SMEM);

    k_qkv<<<HB, 256, Q_SMEM>>>(x, Wq, Wk, Wv);
    k_attn<<<HB, 512, AT_SMEM>>>();
    k_out<<<dim3(4, BB), 256, O_SMEM>>>(Wo, out);
}

// round 7
// speedup vs baseline: 1.7737x; 1.7737x over previous
#include <cuda_runtime.h>
#include <cuda_fp16.h>
#include <cstdint>

#define BB 24
#define DM 128
#define HH 8
#define DK 16
#define LL 512
#define HB (HH*BB)   // 192

__device__ float g_Q[HB*DK*LL];       // [hb][k][l]
__device__ float g_K[HB*DK*LL];
__device__ float g_V[HB*DK*LL];
__device__ float g_head[BB*DM*LL];    // [b][h*16+v][l]

// ---- mma/ldmatrix helpers ----
__device__ __forceinline__ uint32_t smem_u32(const void* p) {
    uint32_t a;
    asm("{ .reg .u64 t; cvta.to.shared.u64 t, %1; cvt.u32.u64 %0, t; }" : "=r"(a) : "l"(p));
    return a;
}
__device__ __forceinline__ void ldsm4(uint32_t* r, uint32_t a) {
    asm volatile("ldmatrix.sync.aligned.m8n8.x4.shared.b16 {%0,%1,%2,%3}, [%4];"
        : "=r"(r[0]), "=r"(r[1]), "=r"(r[2]), "=r"(r[3]) : "r"(a));
}
__device__ __forceinline__ void ldsm4t(uint32_t* r, uint32_t a) {
    asm volatile("ldmatrix.sync.aligned.m8n8.x4.trans.shared.b16 {%0,%1,%2,%3}, [%4];"
        : "=r"(r[0]), "=r"(r[1]), "=r"(r[2]), "=r"(r[3]) : "r"(a));
}
__device__ __forceinline__ void mma_f16(float* d, const uint32_t* a, const uint32_t* b) {
    asm volatile("mma.sync.aligned.m16n8k16.row.col.f32.f16.f16.f32 "
        "{%0,%1,%2,%3}, {%4,%5,%6,%7}, {%8,%9}, {%0,%1,%2,%3};"
        : "+f"(d[0]), "+f"(d[1]), "+f"(d[2]), "+f"(d[3])
        : "r"(a[0]), "r"(a[1]), "r"(a[2]), "r"(a[3]), "r"(b[0]), "r"(b[1]));
}
__device__ __forceinline__ float ex2f(float x) {
    float r; asm("ex2.approx.f32 %0, %1;" : "=f"(r) : "f"(x)); return r;
}
__device__ __forceinline__ void packhl(float p0, float p1, uint32_t& h, uint32_t& l) {
    __half2 hh = __floats2half2_rn(p0, p1);
    float2 f = __half22float2(hh);
    __half2 ll = __floats2half2_rn(p0 - f.x, p1 - f.y);
    h = *(uint32_t*)&hh; l = *(uint32_t*)&ll;
}

// =====================================================================
// Kernel 1: QKV via mma.sync fp16 hi/lo. Grid 192 (hb), 256 thr.
// W staged [m][k] (A, non-trans); x staged [d][l] natural (B, trans ldsm).
// =====================================================================
#define QW_H 0          // 48*136*2 = 13056
#define QW_L 13056
#define QX_H 26112      // 128*136*2 = 34816
#define QX_L 60928
#define Q_SMEM 95744

__global__ __launch_bounds__(256) void k_qkv(const float* __restrict__ x,
                                             const float* __restrict__ Wq,
                                             const float* __restrict__ Wk,
                                             const float* __restrict__ Wv)
{
    extern __shared__ char smc[];
    const uint32_t su = smem_u32(smc);
    __half* sWh = (__half*)(smc + QW_H);
    __half* sWl = (__half*)(smc + QW_L);
    __half* sXh = (__half*)(smc + QX_H);
    __half* sXl = (__half*)(smc + QX_L);
    const int t = threadIdx.x, w = t >> 5, ln = t & 31;
    const int hb = blockIdx.x, b = hb % BB;
    const int rsel = ln & 15;
    const uint32_t csel = (uint32_t)(ln >> 4) * 16;
    const int trow = (ln & 7) + ((ln >> 4) << 3);
    const uint32_t tcb = (uint32_t)((ln >> 3) & 1) * 16;

    // stage W (48x128) hi/lo: vectorized, conflict-free
    for (int i4 = t; i4 < 1536; i4 += 256) {
        int r = i4 >> 5, c4 = i4 & 31;
        const float* src = (r < 16) ? (Wq + (size_t)hb*2048 + r*128)
                         : (r < 32) ? (Wk + (size_t)hb*2048 + (r-16)*128)
                                    : (Wv + (size_t)hb*2048 + (r-32)*128);
        float4 v = *(const float4*)(src + c4*4);
        uint32_t h0,l0,h1,l1;
        packhl(v.x, v.y, h0, l0); packhl(v.z, v.w, h1, l1);
        uint2 uh; uh.x = h0; uh.y = h1;
        uint2 ul; ul.x = l0; ul.y = l1;
        *(uint2*)&sWh[r*136 + c4*4] = uh;
        *(uint2*)&sWl[r*136 + c4*4] = ul;
    }

    for (int lt = 0; lt < 4; ++lt) {
        __syncthreads();
        // stage x chunk [d][l] natural layout (no transpose)
        for (int i4 = t; i4 < 4096; i4 += 256) {
            int d = i4 >> 5, l4 = i4 & 31;
            float4 xv = *(const float4*)(x + (size_t)b*65536 + (size_t)d*512 + lt*128 + l4*4);
            uint32_t h0,l0,h1,l1;
            packhl(xv.x, xv.y, h0, l0); packhl(xv.z, xv.w, h1, l1);
            uint2 uh; uh.x = h0; uh.y = h1;
            uint2 ul; ul.x = l0; ul.y = l1;
            *(uint2*)&sXh[d*136 + l4*4] = uh;
            *(uint2*)&sXl[d*136 + l4*4] = ul;
        }
        __syncthreads();

        float acc[3][2][4];
        #pragma unroll
        for (int mt = 0; mt < 3; ++mt)
            #pragma unroll
            for (int nt = 0; nt < 2; ++nt)
                #pragma unroll
                for (int r = 0; r < 4; ++r) acc[mt][nt][r] = 0.f;

        #pragma unroll
        for (int kt = 0; kt < 8; ++kt) {
            uint32_t bh[2][2], bl[2][2], r4[4];
            uint32_t ad = su + QX_H + (uint32_t)((kt*16 + trow)*272) + (uint32_t)(w*16)*2 + tcb;
            ldsm4t(r4, ad);
            bh[0][0]=r4[0]; bh[0][1]=r4[2]; bh[1][0]=r4[1]; bh[1][1]=r4[3];
            ldsm4t(r4, ad + (QX_L - QX_H));
            bl[0][0]=r4[0]; bl[0][1]=r4[2]; bl[1][0]=r4[1]; bl[1][1]=r4[3];
            #pragma unroll
            for (int mt = 0; mt < 3; ++mt) {
                uint32_t ah[4], al[4];
                uint32_t aad = su + QW_H + (uint32_t)((mt*16 + rsel)*272) + csel + kt*32;
                ldsm4(ah, aad);
                ldsm4(al, aad + (QW_L - QW_H));
                #pragma unroll
                for (int nt = 0; nt < 2; ++nt) {
                    mma_f16(acc[mt][nt], ah, bh[nt]);
                    mma_f16(acc[mt][nt], ah, bl[nt]);
                    mma_f16(acc[mt][nt], al, bh[nt]);
                }
            }
        }

        #pragma unroll
        for (int mt = 0; mt < 3; ++mt) {
            float* dst = (mt == 0) ? g_Q : (mt == 1) ? g_K : g_V;
            dst += (size_t)hb * 8192;
            #pragma unroll
            for (int nt = 0; nt < 2; ++nt) {
                int rr = ln >> 2;
                int cc = lt*128 + w*16 + nt*8 + (ln & 3)*2;
                float2 v0; v0.x = acc[mt][nt][0]; v0.y = acc[mt][nt][1];
                float2 v1; v1.x = acc[mt][nt][2]; v1.y = acc[mt][nt][3];
                *(float2*)&dst[(size_t)rr*512 + cc]     = v0;
                *(float2*)&dst[(size_t)(rr+8)*512 + cc] = v1;
            }
        }
    }
}

// =====================================================================
// Kernel 2: attention, flash-style mma.sync fp16 hi/lo.
// Q,K,V all staged [k][l] natural (pitch 520 halves); K/Q frags via
// trans ldmatrix, V via non-trans (as R5).
// =====================================================================
#define AT_QH 0
#define AT_QL 16640
#define AT_KH 33280
#define AT_KL 49920
#define AT_VH 66560
#define AT_VL 83200
#define AT_SMEM 99840

__global__ __launch_bounds__(512) void k_attn()
{
    extern __shared__ char smc[];
    const uint32_t su = smem_u32(smc);
    const int t = threadIdx.x, w = t >> 5, ln = t & 31;
    const int hb = blockIdx.x, b = hb % BB, h = hb / BB;

    __half* sQh = (__half*)(smc + AT_QH);
    __half* sQl = (__half*)(smc + AT_QL);
    __half* sKh = (__half*)(smc + AT_KH);
    __half* sKl = (__half*)(smc + AT_KL);
    __half* sVh = (__half*)(smc + AT_VH);
    __half* sVl = (__half*)(smc + AT_VL);

    const float* gq = g_Q + (size_t)hb * 8192;
    const float* gk = g_K + (size_t)hb * 8192;
    const float* gv = g_V + (size_t)hb * 8192;

    for (int i4 = t; i4 < 2048; i4 += 512) {
        int k = i4 >> 7, l4 = i4 & 127;
        int so = k*520 + l4*4;
        uint32_t h0,l0,h1,l1;
        float4 q4 = *(const float4*)(gq + k*512 + l4*4);
        packhl(q4.x,q4.y,h0,l0); packhl(q4.z,q4.w,h1,l1);
        { uint2 uh={h0,h1}, ul={l0,l1}; *(uint2*)&sQh[so]=uh; *(uint2*)&sQl[so]=ul; }
        float4 k4 = *(const float4*)(gk + k*512 + l4*4);
        packhl(k4.x,k4.y,h0,l0); packhl(k4.z,k4.w,h1,l1);
        { uint2 uh={h0,h1}, ul={l0,l1}; *(uint2*)&sKh[so]=uh; *(uint2*)&sKl[so]=ul; }
        float4 v4 = *(const float4*)(gv + k*512 + l4*4);
        packhl(v4.x,v4.y,h0,l0); packhl(v4.z,v4.w,h1,l1);
        { uint2 uh={h0,h1}, ul={l0,l1}; *(uint2*)&sVh[so]=uh; *(uint2*)&sVl[so]=ul; }
    }
    __syncthreads();

    const int rsel = ln & 15;
    const uint32_t csel = (uint32_t)(ln >> 4) * 16;
    const int trow = (ln & 7) + ((ln >> 4) << 3);
    const uint32_t tcb = (uint32_t)((ln >> 3) & 1) * 16;

    // resident K A-fragments via trans ldmatrix from [k][m]
    uint32_t kh[2][4], kl[2][4];
    #pragma unroll
    for (int mt = 0; mt < 2; ++mt) {
        uint32_t ad = su + AT_KH + (uint32_t)(trow*1040) + (uint32_t)((w*32 + mt*16)*2) + tcb;
        ldsm4t(kh[mt], ad);
        ldsm4t(kl[mt], ad + (AT_KL - AT_KH));
    }

    float mx[2][2], dn[2][2], O[2][2][4];
    #pragma unroll
    for (int mt = 0; mt < 2; ++mt)
        #pragma unroll
        for (int j = 0; j < 2; ++j) {
            mx[mt][j] = -1e30f; dn[mt][j] = 0.f;
            #pragma unroll
            for (int r = 0; r < 4; ++r) O[mt][j][r] = 0.f;
        }

    const float C = 0.36067376022224085f;   // 0.25 * log2(e)

    for (int c = 0; c < 16; ++c) {
        // Q B-frags via trans ldmatrix from [k][l]
        uint32_t qbh[4][2], qbl[4][2];
        #pragma unroll
        for (int q = 0; q < 2; ++q) {
            uint32_t r4[4];
            uint32_t ad = su + AT_QH + (uint32_t)(trow*1040) + (uint32_t)((c*32 + q*16)*2) + tcb;
            ldsm4t(r4, ad);
            qbh[2*q][0]=r4[0]; qbh[2*q][1]=r4[2]; qbh[2*q+1][0]=r4[1]; qbh[2*q+1][1]=r4[3];
            ldsm4t(r4, ad + (AT_QL - AT_QH));
            qbl[2*q][0]=r4[0]; qbl[2*q][1]=r4[2]; qbl[2*q+1][0]=r4[1]; qbl[2*q+1][1]=r4[3];
        }

        float s[2][4][4];
        #pragma unroll
        for (int mt = 0; mt < 2; ++mt)
            #pragma unroll
            for (int nt = 0; nt < 4; ++nt) {
                #pragma unroll
                for (int r = 0; r < 4; ++r) s[mt][nt][r] = 0.f;
                mma_f16(s[mt][nt], kh[mt], qbh[nt]);
                mma_f16(s[mt][nt], kh[mt], qbl[nt]);
                mma_f16(s[mt][nt], kl[mt], qbh[nt]);
            }

        #pragma unroll
        for (int mt = 0; mt < 2; ++mt) {
            float cA = -1e30f, cB = -1e30f;
            #pragma unroll
            for (int nt = 0; nt < 4; ++nt) {
                cA = fmaxf(cA, fmaxf(s[mt][nt][0], s[mt][nt][1]));
                cB = fmaxf(cB, fmaxf(s[mt][nt][2], s[mt][nt][3]));
            }
            cA = fmaxf(cA, __shfl_xor_sync(0xffffffffu, cA, 1));
            cA = fmaxf(cA, __shfl_xor_sync(0xffffffffu, cA, 2));
            cB = fmaxf(cB, __shfl_xor_sync(0xffffffffu, cB, 1));
            cB = fmaxf(cB, __shfl_xor_sync(0xffffffffu, cB, 2));
            float mA = fmaxf(mx[mt][0], cA), mB = fmaxf(mx[mt][1], cB);
            float sA = ex2f((mx[mt][0] - mA) * C), sB = ex2f((mx[mt][1] - mB) * C);
            mx[mt][0] = mA; mx[mt][1] = mB;
            dn[mt][0] *= sA; dn[mt][1] *= sB;
            #pragma unroll
            for (int vt = 0; vt < 2; ++vt) {
                O[mt][vt][0] *= sA; O[mt][vt][1] *= sA;
                O[mt][vt][2] *= sB; O[mt][vt][3] *= sB;
            }
            #pragma unroll
            for (int nt = 0; nt < 4; ++nt) {
                float p0 = ex2f((s[mt][nt][0] - mA) * C);
                float p1 = ex2f((s[mt][nt][1] - mA) * C);
                float p2 = ex2f((s[mt][nt][2] - mB) * C);
                float p3 = ex2f((s[mt][nt][3] - mB) * C);
                dn[mt][0] += p0 + p1; dn[mt][1] += p2 + p3;
                s[mt][nt][0] = p0; s[mt][nt][1] = p1;
                s[mt][nt][2] = p2; s[mt][nt][3] = p3;
            }
        }

        #pragma unroll
        for (int st = 0; st < 2; ++st) {
            uint32_t vbh[2][2], vbl[2][2], r4[4];
            uint32_t ad = su + AT_VH + (uint32_t)(rsel * 1040 + (c*32 + st*16) * 2) + csel;
            ldsm4(r4, ad);
            vbh[0][0]=r4[0]; vbh[0][1]=r4[2]; vbh[1][0]=r4[1]; vbh[1][1]=r4[3];
            ldsm4(r4, ad + (AT_VL - AT_VH));
            vbl[0][0]=r4[0]; vbl[0][1]=r4[2]; vbl[1][0]=r4[1]; vbl[1][1]=r4[3];

            #pragma unroll
            for (int mt = 0; mt < 2; ++mt) {
                uint32_t ah[4], al[4];
                packhl(s[mt][2*st][0],   s[mt][2*st][1],   ah[0], al[0]);
                packhl(s[mt][2*st][2],   s[mt][2*st][3],   ah[1], al[1]);
                packhl(s[mt][2*st+1][0], s[mt][2*st+1][1], ah[2], al[2]);
                packhl(s[mt][2*st+1][2], s[mt][2*st+1][3], ah[3], al[3]);
                #pragma unroll
                for (int vt = 0; vt < 2; ++vt) {
                    mma_f16(O[mt][vt], ah, vbh[vt]);
                    mma_f16(O[mt][vt], ah, vbl[vt]);
                    mma_f16(O[mt][vt], al, vbh[vt]);
                }
            }
        }
    }

    #pragma unroll
    for (int mt = 0; mt < 2; ++mt)
        #pragma unroll
        for (int j = 0; j < 2; ++j) {
            dn[mt][j] += __shfl_xor_sync(0xffffffffu, dn[mt][j], 1);
            dn[mt][j] += __shfl_xor_sync(0xffffffffu, dn[mt][j], 2);
        }

    float* dst = g_head + ((size_t)b * DM + h * DK) * LL;
    #pragma unroll
    for (int mt = 0; mt < 2; ++mt)
        #pragma unroll
        for (int vt = 0; vt < 2; ++vt)
            #pragma unroll
            for (int r = 0; r < 4; ++r) {
                int m = w*32 + mt*16 + (ln >> 2) + ((r >> 1) & 1) * 8;
                int v = vt*8 + (ln & 3)*2 + (r & 1);
                dst[(size_t)v * LL + m] = O[mt][vt][r] / dn[mt][(r >> 1) & 1];
            }
}

// =====================================================================
// Kernel 3: out = Wo @ head via mma.sync fp16 hi/lo.
// Wo staged [m][k] (A non-trans); head staged [d][l] natural (B trans).
// Grid (4 lt, 24 b), 256 thr.
// =====================================================================
#define OW_H 0          // 128*136*2 = 34816
#define OW_L 34816
#define OX_H 69632
#define OX_L 104448
#define O_SMEM 139264

__global__ __launch_bounds__(256) void k_out(const float* __restrict__ Wo,
                                             float* __restrict__ out)
{
    extern __shared__ char smc[];
    const uint32_t su = smem_u32(smc);
    __half* sWh = (__half*)(smc + OW_H);
    __half* sWl = (__half*)(smc + OW_L);
    __half* sXh = (__half*)(smc + OX_H);
    __half* sXl = (__half*)(smc + OX_L);
    const int t = threadIdx.x, w = t >> 5, ln = t & 31;
    const int lt = blockIdx.x, b = blockIdx.y;
    const int rsel = ln & 15;
    const uint32_t csel = (uint32_t)(ln >> 4) * 16;
    const int trow = (ln & 7) + ((ln >> 4) << 3);
    const uint32_t tcb = (uint32_t)((ln >> 3) & 1) * 16;

    for (int i4 = t; i4 < 4096; i4 += 256) {
        int r = i4 >> 5, c4 = i4 & 31;
        float4 v = *(const float4*)(Wo + (size_t)b*16384 + (size_t)r*128 + c4*4);
        uint32_t h0,l0,h1,l1;
        packhl(v.x, v.y, h0, l0); packhl(v.z, v.w, h1, l1);
        uint2 uh; uh.x = h0; uh.y = h1;
        uint2 ul; ul.x = l0; ul.y = l1;
        *(uint2*)&sWh[r*136 + c4*4] = uh;
        *(uint2*)&sWl[r*136 + c4*4] = ul;
    }
    for (int i4 = t; i4 < 4096; i4 += 256) {
        int d = i4 >> 5, l4 = i4 & 31;
        float4 xv = *(const float4*)(g_head + (size_t)b*65536 + (size_t)d*512 + lt*128 + l4*4);
        uint32_t h0,l0,h1,l1;
        packhl(xv.x, xv.y, h0, l0); packhl(xv.z, xv.w, h1, l1);
        uint2 uh; uh.x = h0; uh.y = h1;
        uint2 ul; ul.x = l0; ul.y = l1;
        *(uint2*)&sXh[d*136 + l4*4] = uh;
        *(uint2*)&sXl[d*136 + l4*4] = ul;
    }
    __syncthreads();

    float acc[8][2][4];
    #pragma unroll
    for (int mt = 0; mt < 8; ++mt)
        #pragma unroll
        for (int nt = 0; nt < 2; ++nt)
            #pragma unroll
            for (int r = 0; r < 4; ++r) acc[mt][nt][r] = 0.f;

    #pragma unroll
    for (int kt = 0; kt < 8; ++kt) {
        uint32_t bh[2][2], bl[2][2], r4[4];
        uint32_t ad = su + OX_H + (uint32_t)((kt*16 + trow)*272) + (uint32_t)(w*16)*2 + tcb;
        ldsm4t(r4, ad);
        bh[0][0]=r4[0]; bh[0][1]=r4[2]; bh[1][0]=r4[1]; bh[1][1]=r4[3];
        ldsm4t(r4, ad + (OX_L - OX_H));
        bl[0][0]=r4[0]; bl[0][1]=r4[2]; bl[1][0]=r4[1]; bl[1][1]=r4[3];
        #pragma unroll
        for (int mt = 0; mt < 8; ++mt) {
            uint32_t ah[4], al[4];
            uint32_t aad = su + OW_H + (uint32_t)((mt*16 + rsel)*272) + csel + kt*32;
            ldsm4(ah, aad);
            ldsm4(al, aad + (OW_L - OW_H));
            #pragma unroll
            for (int nt = 0; nt < 2; ++nt) {
                mma_f16(acc[mt][nt], ah, bh[nt]);
                mma_f16(acc[mt][nt], ah, bl[nt]);
                mma_f16(acc[mt][nt], al, bh[nt]);
            }
        }
    }

    #pragma unroll
    for (int mt = 0; mt < 8; ++mt)
        #pragma unroll
        for (int nt = 0; nt < 2; ++nt) {
            int rr = mt*16 + (ln >> 2);
            int cc = lt*128 + w*16 + nt*8 + (ln & 3)*2;
            float2 v0; v0.x = acc[mt][nt][0]; v0.y = acc[mt][nt][1];
            float2 v1; v1.x = acc[mt][nt][2]; v1.y = acc[mt][nt][3];
            *(float2*)&out[(size_t)b*DM*LL + (size_t)rr*512 + cc]     = v0;
            *(float2*)&out[(size_t)b*DM*LL + (size_t)(rr+8)*512 + cc] = v1;
        }
}

// =====================================================================
extern "C" void kernel_launch(void* const* d_in, const int* in_sizes, int n_in,
                              void* d_out, int out_size)
{
    const float* x  = (const float*)d_in[0];
    const float* Wq = (const float*)d_in[1];
    const float* Wk = (const float*)d_in[2];
    const float* Wv = (const float*)d_in[3];
    const float* Wo = (const float*)d_in[4];
    float* out = (float*)d_out;

    cudaFuncSetAttribute(k_qkv,  cudaFuncAttributeMaxDynamicSharedMemorySize, Q_SMEM);
    cudaFuncSetAttribute(k_attn, cudaFuncAttributeMaxDynamicSharedMemorySize, AT_SMEM);
    cudaFuncSetAttribute(k_out,  cudaFuncAttributeMaxDynamicSharedMemorySize, O_SMEM);

    k_qkv<<<HB, 256, Q_SMEM>>>(x, Wq, Wk, Wv);
    k_attn<<<HB, 512, AT_SMEM>>>();
    k_out<<<dim3(4, BB), 256, O_SMEM>>>(Wo, out);
}

// round 8
// speedup vs baseline: 2.1102x; 1.1897x over previous
#include <cuda_runtime.h>
#include <cuda_fp16.h>
#include <cstdint>

#define BB 24
#define DM 128
#define HH 8
#define DK 16
#define LL 512
#define HB (HH*BB)   // 192

__device__ float g_Q[HB*DK*LL];       // [hb][k][l]
__device__ float g_K[HB*DK*LL];
__device__ float g_V[HB*DK*LL];
__device__ float g_head[BB*DM*LL];    // [b][h*16+v][l]

// ---- mma/ldmatrix helpers ----
__device__ __forceinline__ uint32_t smem_u32(const void* p) {
    uint32_t a;
    asm("{ .reg .u64 t; cvta.to.shared.u64 t, %1; cvt.u32.u64 %0, t; }" : "=r"(a) : "l"(p));
    return a;
}
__device__ __forceinline__ void ldsm4(uint32_t* r, uint32_t a) {
    asm volatile("ldmatrix.sync.aligned.m8n8.x4.shared.b16 {%0,%1,%2,%3}, [%4];"
        : "=r"(r[0]), "=r"(r[1]), "=r"(r[2]), "=r"(r[3]) : "r"(a));
}
__device__ __forceinline__ void ldsm4t(uint32_t* r, uint32_t a) {
    asm volatile("ldmatrix.sync.aligned.m8n8.x4.trans.shared.b16 {%0,%1,%2,%3}, [%4];"
        : "=r"(r[0]), "=r"(r[1]), "=r"(r[2]), "=r"(r[3]) : "r"(a));
}
__device__ __forceinline__ void mma_f16(float* d, const uint32_t* a, const uint32_t* b) {
    asm volatile("mma.sync.aligned.m16n8k16.row.col.f32.f16.f16.f32 "
        "{%0,%1,%2,%3}, {%4,%5,%6,%7}, {%8,%9}, {%0,%1,%2,%3};"
        : "+f"(d[0]), "+f"(d[1]), "+f"(d[2]), "+f"(d[3])
        : "r"(a[0]), "r"(a[1]), "r"(a[2]), "r"(a[3]), "r"(b[0]), "r"(b[1]));
}
__device__ __forceinline__ float ex2f(float x) {
    float r; asm("ex2.approx.f32 %0, %1;" : "=f"(r) : "f"(x)); return r;
}
__device__ __forceinline__ void packhl(float p0, float p1, uint32_t& h, uint32_t& l) {
    __half2 hh = __floats2half2_rn(p0, p1);
    float2 f = __half22float2(hh);
    __half2 ll = __floats2half2_rn(p0 - f.x, p1 - f.y);
    h = *(uint32_t*)&hh; l = *(uint32_t*)&ll;
}
__device__ __forceinline__ uint32_t packh(float p0, float p1) {
    __half2 hh = __floats2half2_rn(p0, p1);
    return *(uint32_t*)&hh;
}

// =====================================================================
// Kernel 1: QKV via mma.sync fp16 hi/lo. Grid 384 = (hb, lt-half).
// 256 thr. W staged [m][k] (A); x staged [d][l] natural (B, trans ldsm).
// =====================================================================
#define QW_H 0          // 48*136*2 = 13056
#define QW_L 13056
#define QX_H 26112      // 128*136*2 = 34816
#define QX_L 60928
#define Q_SMEM 95744

__global__ __launch_bounds__(256) void k_qkv(const float* __restrict__ x,
                                             const float* __restrict__ Wq,
                                             const float* __restrict__ Wk,
                                             const float* __restrict__ Wv)
{
    extern __shared__ char smc[];
    const uint32_t su = smem_u32(smc);
    __half* sWh = (__half*)(smc + QW_H);
    __half* sWl = (__half*)(smc + QW_L);
    __half* sXh = (__half*)(smc + QX_H);
    __half* sXl = (__half*)(smc + QX_L);
    const int t = threadIdx.x, w = t >> 5, ln = t & 31;
    const int hb = blockIdx.x >> 1, half = blockIdx.x & 1;
    const int b = hb % BB;
    const int rsel = ln & 15;
    const uint32_t csel = (uint32_t)(ln >> 4) * 16;
    const int trow = (ln & 7) + ((ln >> 4) << 3);
    const uint32_t tcb = (uint32_t)((ln >> 3) & 1) * 16;

    for (int i4 = t; i4 < 1536; i4 += 256) {
        int r = i4 >> 5, c4 = i4 & 31;
        const float* src = (r < 16) ? (Wq + (size_t)hb*2048 + r*128)
                         : (r < 32) ? (Wk + (size_t)hb*2048 + (r-16)*128)
                                    : (Wv + (size_t)hb*2048 + (r-32)*128);
        float4 v = *(const float4*)(src + c4*4);
        uint32_t h0,l0,h1,l1;
        packhl(v.x, v.y, h0, l0); packhl(v.z, v.w, h1, l1);
        uint2 uh; uh.x = h0; uh.y = h1;
        uint2 ul; ul.x = l0; ul.y = l1;
        *(uint2*)&sWh[r*136 + c4*4] = uh;
        *(uint2*)&sWl[r*136 + c4*4] = ul;
    }

    for (int lt = half*2; lt < half*2 + 2; ++lt) {
        __syncthreads();
        for (int i4 = t; i4 < 4096; i4 += 256) {
            int d = i4 >> 5, l4 = i4 & 31;
            float4 xv = *(const float4*)(x + (size_t)b*65536 + (size_t)d*512 + lt*128 + l4*4);
            uint32_t h0,l0,h1,l1;
            packhl(xv.x, xv.y, h0, l0); packhl(xv.z, xv.w, h1, l1);
            uint2 uh; uh.x = h0; uh.y = h1;
            uint2 ul; ul.x = l0; ul.y = l1;
            *(uint2*)&sXh[d*136 + l4*4] = uh;
            *(uint2*)&sXl[d*136 + l4*4] = ul;
        }
        __syncthreads();

        float acc[3][2][4];
        #pragma unroll
        for (int mt = 0; mt < 3; ++mt)
            #pragma unroll
            for (int nt = 0; nt < 2; ++nt)
                #pragma unroll
                for (int r = 0; r < 4; ++r) acc[mt][nt][r] = 0.f;

        #pragma unroll
        for (int kt = 0; kt < 8; ++kt) {
            uint32_t bh[2][2], bl[2][2], r4[4];
            uint32_t ad = su + QX_H + (uint32_t)((kt*16 + trow)*272) + (uint32_t)(w*16)*2 + tcb;
            ldsm4t(r4, ad);
            bh[0][0]=r4[0]; bh[0][1]=r4[2]; bh[1][0]=r4[1]; bh[1][1]=r4[3];
            ldsm4t(r4, ad + (QX_L - QX_H));
            bl[0][0]=r4[0]; bl[0][1]=r4[2]; bl[1][0]=r4[1]; bl[1][1]=r4[3];
            #pragma unroll
            for (int mt = 0; mt < 3; ++mt) {
                uint32_t ah[4], al[4];
                uint32_t aad = su + QW_H + (uint32_t)((mt*16 + rsel)*272) + csel + kt*32;
                ldsm4(ah, aad);
                ldsm4(al, aad + (QW_L - QW_H));
                #pragma unroll
                for (int nt = 0; nt < 2; ++nt) {
                    mma_f16(acc[mt][nt], ah, bh[nt]);
                    mma_f16(acc[mt][nt], ah, bl[nt]);
                    mma_f16(acc[mt][nt], al, bh[nt]);
                }
            }
        }

        #pragma unroll
        for (int mt = 0; mt < 3; ++mt) {
            float* dst = (mt == 0) ? g_Q : (mt == 1) ? g_K : g_V;
            dst += (size_t)hb * 8192;
            #pragma unroll
            for (int nt = 0; nt < 2; ++nt) {
                int rr = ln >> 2;
                int cc = lt*128 + w*16 + nt*8 + (ln & 3)*2;
                float2 v0; v0.x = acc[mt][nt][0]; v0.y = acc[mt][nt][1];
                float2 v1; v1.x = acc[mt][nt][2]; v1.y = acc[mt][nt][3];
                *(float2*)&dst[(size_t)rr*512 + cc]     = v0;
                *(float2*)&dst[(size_t)(rr+8)*512 + cc] = v1;
            }
        }
    }
}

// =====================================================================
// Kernel 2: attention, flash-style mma.sync fp16 hi/lo.
// Grid 192 (hb), 512 thr. AV uses 2-term (P_hi*V_hi + P_hi*V_lo).
// =====================================================================
#define AT_QH 0
#define AT_QL 16640
#define AT_KH 33280
#define AT_KL 49920
#define AT_VH 66560
#define AT_VL 83200
#define AT_SMEM 99840

__global__ __launch_bounds__(512) void k_attn()
{
    extern __shared__ char smc[];
    const uint32_t su = smem_u32(smc);
    const int t = threadIdx.x, w = t >> 5, ln = t & 31;
    const int hb = blockIdx.x, b = hb % BB, h = hb / BB;

    __half* sQh = (__half*)(smc + AT_QH);
    __half* sQl = (__half*)(smc + AT_QL);
    __half* sKh = (__half*)(smc + AT_KH);
    __half* sKl = (__half*)(smc + AT_KL);
    __half* sVh = (__half*)(smc + AT_VH);
    __half* sVl = (__half*)(smc + AT_VL);

    const float* gq = g_Q + (size_t)hb * 8192;
    const float* gk = g_K + (size_t)hb * 8192;
    const float* gv = g_V + (size_t)hb * 8192;

    for (int i4 = t; i4 < 2048; i4 += 512) {
        int k = i4 >> 7, l4 = i4 & 127;
        int so = k*520 + l4*4;
        uint32_t h0,l0,h1,l1;
        float4 q4 = *(const float4*)(gq + k*512 + l4*4);
        packhl(q4.x,q4.y,h0,l0); packhl(q4.z,q4.w,h1,l1);
        { uint2 uh={h0,h1}, ul={l0,l1}; *(uint2*)&sQh[so]=uh; *(uint2*)&sQl[so]=ul; }
        float4 k4 = *(const float4*)(gk + k*512 + l4*4);
        packhl(k4.x,k4.y,h0,l0); packhl(k4.z,k4.w,h1,l1);
        { uint2 uh={h0,h1}, ul={l0,l1}; *(uint2*)&sKh[so]=uh; *(uint2*)&sKl[so]=ul; }
        float4 v4 = *(const float4*)(gv + k*512 + l4*4);
        packhl(v4.x,v4.y,h0,l0); packhl(v4.z,v4.w,h1,l1);
        { uint2 uh={h0,h1}, ul={l0,l1}; *(uint2*)&sVh[so]=uh; *(uint2*)&sVl[so]=ul; }
    }
    __syncthreads();

    const int rsel = ln & 15;
    const uint32_t csel = (uint32_t)(ln >> 4) * 16;
    const int trow = (ln & 7) + ((ln >> 4) << 3);
    const uint32_t tcb = (uint32_t)((ln >> 3) & 1) * 16;

    uint32_t kh[2][4], kl[2][4];
    #pragma unroll
    for (int mt = 0; mt < 2; ++mt) {
        uint32_t ad = su + AT_KH + (uint32_t)(trow*1040) + (uint32_t)((w*32 + mt*16)*2) + tcb;
        ldsm4t(kh[mt], ad);
        ldsm4t(kl[mt], ad + (AT_KL - AT_KH));
    }

    float mx[2][2], dn[2][2], O[2][2][4];
    #pragma unroll
    for (int mt = 0; mt < 2; ++mt)
        #pragma unroll
        for (int j = 0; j < 2; ++j) {
            mx[mt][j] = -1e30f; dn[mt][j] = 0.f;
            #pragma unroll
            for (int r = 0; r < 4; ++r) O[mt][j][r] = 0.f;
        }

    const float C = 0.36067376022224085f;   // 0.25 * log2(e)

    for (int c = 0; c < 16; ++c) {
        uint32_t qbh[4][2], qbl[4][2];
        #pragma unroll
        for (int q = 0; q < 2; ++q) {
            uint32_t r4[4];
            uint32_t ad = su + AT_QH + (uint32_t)(trow*1040) + (uint32_t)((c*32 + q*16)*2) + tcb;
            ldsm4t(r4, ad);
            qbh[2*q][0]=r4[0]; qbh[2*q][1]=r4[2]; qbh[2*q+1][0]=r4[1]; qbh[2*q+1][1]=r4[3];
            ldsm4t(r4, ad + (AT_QL - AT_QH));
            qbl[2*q][0]=r4[0]; qbl[2*q][1]=r4[2]; qbl[2*q+1][0]=r4[1]; qbl[2*q+1][1]=r4[3];
        }

        float s[2][4][4];
        #pragma unroll
        for (int mt = 0; mt < 2; ++mt)
            #pragma unroll
            for (int nt = 0; nt < 4; ++nt) {
                #pragma unroll
                for (int r = 0; r < 4; ++r) s[mt][nt][r] = 0.f;
                mma_f16(s[mt][nt], kh[mt], qbh[nt]);
                mma_f16(s[mt][nt], kh[mt], qbl[nt]);
                mma_f16(s[mt][nt], kl[mt], qbh[nt]);
            }

        #pragma unroll
        for (int mt = 0; mt < 2; ++mt) {
            float cA = -1e30f, cB = -1e30f;
            #pragma unroll
            for (int nt = 0; nt < 4; ++nt) {
                cA = fmaxf(cA, fmaxf(s[mt][nt][0], s[mt][nt][1]));
                cB = fmaxf(cB, fmaxf(s[mt][nt][2], s[mt][nt][3]));
            }
            cA = fmaxf(cA, __shfl_xor_sync(0xffffffffu, cA, 1));
            cA = fmaxf(cA, __shfl_xor_sync(0xffffffffu, cA, 2));
            cB = fmaxf(cB, __shfl_xor_sync(0xffffffffu, cB, 1));
            cB = fmaxf(cB, __shfl_xor_sync(0xffffffffu, cB, 2));
            float mA = fmaxf(mx[mt][0], cA), mB = fmaxf(mx[mt][1], cB);
            float sA = ex2f((mx[mt][0] - mA) * C), sB = ex2f((mx[mt][1] - mB) * C);
            mx[mt][0] = mA; mx[mt][1] = mB;
            dn[mt][0] *= sA; dn[mt][1] *= sB;
            #pragma unroll
            for (int vt = 0; vt < 2; ++vt) {
                O[mt][vt][0] *= sA; O[mt][vt][1] *= sA;
                O[mt][vt][2] *= sB; O[mt][vt][3] *= sB;
            }
            #pragma unroll
            for (int nt = 0; nt < 4; ++nt) {
                float p0 = ex2f((s[mt][nt][0] - mA) * C);
                float p1 = ex2f((s[mt][nt][1] - mA) * C);
                float p2 = ex2f((s[mt][nt][2] - mB) * C);
                float p3 = ex2f((s[mt][nt][3] - mB) * C);
                dn[mt][0] += p0 + p1; dn[mt][1] += p2 + p3;
                s[mt][nt][0] = p0; s[mt][nt][1] = p1;
                s[mt][nt][2] = p2; s[mt][nt][3] = p3;
            }
        }

        #pragma unroll
        for (int st = 0; st < 2; ++st) {
            uint32_t vbh[2][2], vbl[2][2], r4[4];
            uint32_t ad = su + AT_VH + (uint32_t)(rsel * 1040 + (c*32 + st*16) * 2) + csel;
            ldsm4(r4, ad);
            vbh[0][0]=r4[0]; vbh[0][1]=r4[2]; vbh[1][0]=r4[1]; vbh[1][1]=r4[3];
            ldsm4(r4, ad + (AT_VL - AT_VH));
            vbl[0][0]=r4[0]; vbl[0][1]=r4[2]; vbl[1][0]=r4[1]; vbl[1][1]=r4[3];

            #pragma unroll
            for (int mt = 0; mt < 2; ++mt) {
                uint32_t ah[4];
                ah[0] = packh(s[mt][2*st][0],   s[mt][2*st][1]);
                ah[1] = packh(s[mt][2*st][2],   s[mt][2*st][3]);
                ah[2] = packh(s[mt][2*st+1][0], s[mt][2*st+1][1]);
                ah[3] = packh(s[mt][2*st+1][2], s[mt][2*st+1][3]);
                #pragma unroll
                for (int vt = 0; vt < 2; ++vt) {
                    mma_f16(O[mt][vt], ah, vbh[vt]);
                    mma_f16(O[mt][vt], ah, vbl[vt]);
                }
            }
        }
    }

    float inv[2][2];
    #pragma unroll
    for (int mt = 0; mt < 2; ++mt)
        #pragma unroll
        for (int j = 0; j < 2; ++j) {
            dn[mt][j] += __shfl_xor_sync(0xffffffffu, dn[mt][j], 1);
            dn[mt][j] += __shfl_xor_sync(0xffffffffu, dn[mt][j], 2);
            inv[mt][j] = 1.0f / dn[mt][j];
        }

    float* dst = g_head + ((size_t)b * DM + h * DK) * LL;
    #pragma unroll
    for (int mt = 0; mt < 2; ++mt)
        #pragma unroll
        for (int vt = 0; vt < 2; ++vt)
            #pragma unroll
            for (int r = 0; r < 4; ++r) {
                int m = w*32 + mt*16 + (ln >> 2) + ((r >> 1) & 1) * 8;
                int v = vt*8 + (ln & 3)*2 + (r & 1);
                dst[(size_t)v * LL + m] = O[mt][vt][r] * inv[mt][(r >> 1) & 1];
            }
}

// =====================================================================
// Kernel 3: out = Wo @ head. Grid (8 lt of 64 l, 24 b), 256 thr.
// Warps: lg = w&3 (16-l group), mh = w>>2 (4 mt tiles each).
// =====================================================================
#define OW_H 0          // 128*136*2 = 34816
#define OW_L 34816
#define OX_H 69632      // 128*72*2 = 18432
#define OX_L 88064
#define O_SMEM 106496

__global__ __launch_bounds__(256) void k_out(const float* __restrict__ Wo,
                                             float* __restrict__ out)
{
    extern __shared__ char smc[];
    const uint32_t su = smem_u32(smc);
    __half* sWh = (__half*)(smc + OW_H);
    __half* sWl = (__half*)(smc + OW_L);
    __half* sXh = (__half*)(smc + OX_H);
    __half* sXl = (__half*)(smc + OX_L);
    const int t = threadIdx.x, w = t >> 5, ln = t & 31;
    const int lt = blockIdx.x, b = blockIdx.y;
    const int lg = w & 3, mh = w >> 2;
    const int rsel = ln & 15;
    const uint32_t csel = (uint32_t)(ln >> 4) * 16;
    const int trow = (ln & 7) + ((ln >> 4) << 3);
    const uint32_t tcb = (uint32_t)((ln >> 3) & 1) * 16;

    for (int i4 = t; i4 < 4096; i4 += 256) {
        int r = i4 >> 5, c4 = i4 & 31;
        float4 v = *(const float4*)(Wo + (size_t)b*16384 + (size_t)r*128 + c4*4);
        uint32_t h0,l0,h1,l1;
        packhl(v.x, v.y, h0, l0); packhl(v.z, v.w, h1, l1);
        uint2 uh; uh.x = h0; uh.y = h1;
        uint2 ul; ul.x = l0; ul.y = l1;
        *(uint2*)&sWh[r*136 + c4*4] = uh;
        *(uint2*)&sWl[r*136 + c4*4] = ul;
    }
    for (int i4 = t; i4 < 2048; i4 += 256) {
        int d = i4 >> 4, l4 = i4 & 15;
        float4 xv = *(const float4*)(g_head + (size_t)b*65536 + (size_t)d*512 + lt*64 + l4*4);
        uint32_t h0,l0,h1,l1;
        packhl(xv.x, xv.y, h0, l0); packhl(xv.z, xv.w, h1, l1);
        uint2 uh; uh.x = h0; uh.y = h1;
        uint2 ul; ul.x = l0; ul.y = l1;
        *(uint2*)&sXh[d*72 + l4*4] = uh;
        *(uint2*)&sXl[d*72 + l4*4] = ul;
    }
    __syncthreads();

    float acc[4][2][4];
    #pragma unroll
    for (int mt = 0; mt < 4; ++mt)
        #pragma unroll
        for (int nt = 0; nt < 2; ++nt)
            #pragma unroll
            for (int r = 0; r < 4; ++r) acc[mt][nt][r] = 0.f;

    #pragma unroll
    for (int kt = 0; kt < 8; ++kt) {
        uint32_t bh[2][2], bl[2][2], r4[4];
        uint32_t ad = su + OX_H + (uint32_t)((kt*16 + trow)*144) + (uint32_t)(lg*16)*2 + tcb;
        ldsm4t(r4, ad);
        bh[0][0]=r4[0]; bh[0][1]=r4[2]; bh[1][0]=r4[1]; bh[1][1]=r4[3];
        ldsm4t(r4, ad + (OX_L - OX_H));
        bl[0][0]=r4[0]; bl[0][1]=r4[2]; bl[1][0]=r4[1]; bl[1][1]=r4[3];
        #pragma unroll
        for (int mt = 0; mt < 4; ++mt) {
            uint32_t ah[4], al[4];
            uint32_t aad = su + OW_H + (uint32_t)(((mh*4 + mt)*16 + rsel)*272) + csel + kt*32;
            ldsm4(ah, aad);
            ldsm4(al, aad + (OW_L - OW_H));
            #pragma unroll
            for (int nt = 0; nt < 2; ++nt) {
                mma_f16(acc[mt][nt], ah, bh[nt]);
                mma_f16(acc[mt][nt], ah, bl[nt]);
                mma_f16(acc[mt][nt], al, bh[nt]);
            }
        }
    }

    #pragma unroll
    for (int mt = 0; mt < 4; ++mt)
        #pragma unroll
        for (int nt = 0; nt < 2; ++nt) {
            int rr = (mh*4 + mt)*16 + (ln >> 2);
            int cc = lt*64 + lg*16 + nt*8 + (ln & 3)*2;
            float2 v0; v0.x = acc[mt][nt][0]; v0.y = acc[mt][nt][1];
            float2 v1; v1.x = acc[mt][nt][2]; v1.y = acc[mt][nt][3];
            *(float2*)&out[(size_t)b*DM*LL + (size_t)rr*512 + cc]     = v0;
            *(float2*)&out[(size_t)b*DM*LL + (size_t)(rr+8)*512 + cc] = v1;
        }
}

// =====================================================================
extern "C" void kernel_launch(void* const* d_in, const int* in_sizes, int n_in,
                              void* d_out, int out_size)
{
    const float* x  = (const float*)d_in[0];
    const float* Wq = (const float*)d_in[1];
    const float* Wk = (const float*)d_in[2];
    const float* Wv = (const float*)d_in[3];
    const float* Wo = (const float*)d_in[4];
    float* out = (float*)d_out;

    cudaFuncSetAttribute(k_qkv,  cudaFuncAttributeMaxDynamicSharedMemorySize, Q_SMEM);
    cudaFuncSetAttribute(k_attn, cudaFuncAttributeMaxDynamicSharedMemorySize, AT_SMEM);
    cudaFuncSetAttribute(k_out,  cudaFuncAttributeMaxDynamicSharedMemorySize, O_SMEM);

    k_qkv<<<HB * 2, 256, Q_SMEM>>>(x, Wq, Wk, Wv);
    k_attn<<<HB, 512, AT_SMEM>>>();
    k_out<<<dim3(8, BB), 256, O_SMEM>>>(Wo, out);
}